// round 15
// baseline (speedup 1.0000x reference)
#include <cuda_runtime.h>

// Problem constants
constexpr int BB = 2;
constexpr int TT = 2048;
constexpr int CCH = 1024;
constexpr int HH = 16;
constexpr int HD = 64;
constexpr int MM = BB * TT;   // 4096 rows

// Scratch (device globals: allowed; no cudaMalloc anywhere)
__device__ float g_Q[BB * HH * TT * HD];   // [B,H,T,HD]
__device__ float g_K[BB * HH * TT * HD];
__device__ float g_V[BB * HH * TT * HD];
__device__ float g_Y[MM * CCH];            // [B*T, C] attention output

// ---------------------------------------------------------------------------
// SGEMM: C[M,N] = A[M,K=1024] * W[1024,N] + bias[N]
// BM=128, BN=64, BK=16, 256 threads, 8x4 accum per thread.
// MODE 0: A = x param, scatter output into g_Q/g_K/g_V  (N=3072)
// MODE 1: A = g_Y,     write out[m*1024 + n]            (N=1024)
// ---------------------------------------------------------------------------
template <int MODE>
__global__ __launch_bounds__(256)
void sgemm_kernel(const float* __restrict__ A_in, const float* __restrict__ W,
                  const float* __restrict__ bias, float* __restrict__ out, int N)
{
    __shared__ float As[16][132];   // [k][m], padded
    __shared__ float Bs[16][68];    // [k][n], padded

    const float* __restrict__ A = (MODE == 0) ? A_in : g_Y;

    const int n0 = blockIdx.x * 64;
    const int m0 = blockIdx.y * 128;
    const int t  = threadIdx.x;
    const int tx = t & 15;          // 0..15 -> 4 cols each
    const int ty = t >> 4;          // 0..15 -> 8 rows each

    const int arow  = t >> 2;       // 0..63
    const int akcol = (t & 3) << 2; // 0,4,8,12
    const int brow  = t >> 4;       // 0..15
    const int bcol  = (t & 15) << 2;

    float acc[8][4] = {};

    for (int k0 = 0; k0 < CCH; k0 += 16) {
        const float4 a0 = *(const float4*)&A[(size_t)(m0 + arow) * CCH + k0 + akcol];
        const float4 a1 = *(const float4*)&A[(size_t)(m0 + arow + 64) * CCH + k0 + akcol];
        const float4 bv = *(const float4*)&W[(size_t)(k0 + brow) * N + n0 + bcol];

        __syncthreads();
        As[akcol + 0][arow]      = a0.x;
        As[akcol + 1][arow]      = a0.y;
        As[akcol + 2][arow]      = a0.z;
        As[akcol + 3][arow]      = a0.w;
        As[akcol + 0][arow + 64] = a1.x;
        As[akcol + 1][arow + 64] = a1.y;
        As[akcol + 2][arow + 64] = a1.z;
        As[akcol + 3][arow + 64] = a1.w;
        *(float4*)&Bs[brow][bcol] = bv;
        __syncthreads();

        #pragma unroll
        for (int kk = 0; kk < 16; kk++) {
            float a[8], bq[4];
            *(float4*)&a[0] = *(const float4*)&As[kk][ty * 8];
            *(float4*)&a[4] = *(const float4*)&As[kk][ty * 8 + 4];
            *(float4*)&bq[0] = *(const float4*)&Bs[kk][tx * 4];
            #pragma unroll
            for (int i = 0; i < 8; i++)
                #pragma unroll
                for (int j = 0; j < 4; j++)
                    acc[i][j] += a[i] * bq[j];
        }
    }

    const int n = n0 + tx * 4;
    const float4 bvec = *(const float4*)&bias[n];

    if (MODE == 0) {
        // n in [0,3072): section 0=Q,1=K,2=V; within section: head h, dim d
        const int sec = n >> 10;
        const int cc  = n & 1023;
        const int h   = cc >> 6;
        const int d   = cc & 63;
        float* dst = (sec == 0) ? g_Q : ((sec == 1) ? g_K : g_V);
        #pragma unroll
        for (int i = 0; i < 8; i++) {
            const int mg = m0 + ty * 8 + i;
            const int b_ = mg >> 11;          // /2048
            const int tt = mg & (TT - 1);
            float4 v;
            v.x = acc[i][0] + bvec.x;
            v.y = acc[i][1] + bvec.y;
            v.z = acc[i][2] + bvec.z;
            v.w = acc[i][3] + bvec.w;
            *(float4*)&dst[((size_t)((b_ * HH + h) * TT + tt)) * HD + d] = v;
        }
    } else {
        #pragma unroll
        for (int i = 0; i < 8; i++) {
            const int mg = m0 + ty * 8 + i;
            float4 v;
            v.x = acc[i][0] + bvec.x;
            v.y = acc[i][1] + bvec.y;
            v.z = acc[i][2] + bvec.z;
            v.w = acc[i][3] + bvec.w;
            *(float4*)&out[(size_t)mg * CCH + n] = v;
        }
    }
}

// ---------------------------------------------------------------------------
// Flash attention, fp32. One q-row per thread (128 rows / block), KT=32 K/V
// tiles in shared memory, online softmax. Causal. Writes g_Y[B*T, C].
// ---------------------------------------------------------------------------
constexpr int KT = 32;

__global__ __launch_bounds__(128)
void attn_kernel()
{
    __shared__ float Ks[KT * HD];
    __shared__ float Vs[KT * HD];

    const int tid = threadIdx.x;
    // reverse block order: largest (most k-tiles) blocks scheduled first
    const int q0 = (gridDim.x - 1 - blockIdx.x) * 128;
    const int h  = blockIdx.y;
    const int b  = blockIdx.z;
    const int tq = q0 + tid;

    const float* __restrict__ Qp = &g_Q[((size_t)(b * HH + h) * TT + tq) * HD];
    const float* __restrict__ Kbase = &g_K[(size_t)(b * HH + h) * TT * HD];
    const float* __restrict__ Vbase = &g_V[(size_t)(b * HH + h) * TT * HD];

    float q[HD];
    #pragma unroll
    for (int d = 0; d < HD; d += 4) {
        const float4 v = *(const float4*)&Qp[d];
        q[d] = v.x; q[d+1] = v.y; q[d+2] = v.z; q[d+3] = v.w;
    }

    float o[HD];
    #pragma unroll
    for (int d = 0; d < HD; d++) o[d] = 0.f;
    float mrun = -1e30f;
    float l = 0.f;

    const int ntiles = (q0 + 128) / KT;

    for (int kt = 0; kt < ntiles; kt++) {
        const int k0 = kt * KT;

        __syncthreads();
        {
            const float4* __restrict__ Ksrc = (const float4*)(Kbase + (size_t)k0 * HD);
            const float4* __restrict__ Vsrc = (const float4*)(Vbase + (size_t)k0 * HD);
            float4* Kd = (float4*)Ks;
            float4* Vd = (float4*)Vs;
            #pragma unroll
            for (int i = 0; i < (KT * HD / 4) / 128; i++) {
                Kd[tid + i * 128] = Ksrc[tid + i * 128];
                Vd[tid + i * 128] = Vsrc[tid + i * 128];
            }
        }
        __syncthreads();

        if (k0 <= tq) {
            float s[KT];
            #pragma unroll
            for (int j = 0; j < KT; j++) {
                const float* kr = &Ks[j * HD];
                float acc = 0.f;
                #pragma unroll
                for (int d = 0; d < HD; d += 4) {
                    const float4 kv = *(const float4*)&kr[d];
                    acc += q[d]   * kv.x;
                    acc += q[d+1] * kv.y;
                    acc += q[d+2] * kv.z;
                    acc += q[d+3] * kv.w;
                }
                s[j] = (k0 + j <= tq) ? acc * 0.125f : -1e30f;
            }

            float mt = mrun;
            #pragma unroll
            for (int j = 0; j < KT; j++) mt = fmaxf(mt, s[j]);

            const float scale_o = __expf(mrun - mt);
            mrun = mt;
            l *= scale_o;
            #pragma unroll
            for (int d = 0; d < HD; d++) o[d] *= scale_o;

            #pragma unroll
            for (int j = 0; j < KT; j++) {
                const float p = __expf(s[j] - mrun);
                l += p;
                const float* vr = &Vs[j * HD];
                #pragma unroll
                for (int d = 0; d < HD; d += 4) {
                    const float4 vv = *(const float4*)&vr[d];
                    o[d]   += p * vv.x;
                    o[d+1] += p * vv.y;
                    o[d+2] += p * vv.z;
                    o[d+3] += p * vv.w;
                }
            }
        }
    }

    const float inv = 1.f / l;
    float* Yp = &g_Y[((size_t)(b * TT + tq)) * CCH + h * HD];
    #pragma unroll
    for (int d = 0; d < HD; d += 4) {
        float4 v;
        v.x = o[d]   * inv;
        v.y = o[d+1] * inv;
        v.z = o[d+2] * inv;
        v.w = o[d+3] * inv;
        *(float4*)&Yp[d] = v;
    }
}

// ---------------------------------------------------------------------------
// kernel_launch — inputs: x, w_attn, b_attn, w_proj, b_proj ; out: [B,T,C] f32
// ---------------------------------------------------------------------------
extern "C" void kernel_launch(void* const* d_in, const int* in_sizes, int n_in,
                              void* d_out, int out_size)
{
    const float* x      = (const float*)d_in[0];
    const float* w_attn = (const float*)d_in[1];
    const float* b_attn = (const float*)d_in[2];
    const float* w_proj = (const float*)d_in[3];
    const float* b_proj = (const float*)d_in[4];
    float* out = (float*)d_out;

    // 1. QKV GEMM + bias, scattered to [B,H,T,HD] Q/K/V
    sgemm_kernel<0><<<dim3(3 * CCH / 64, MM / 128), 256>>>(x, w_attn, b_attn, nullptr, 3 * CCH);

    // 2. Causal flash attention -> g_Y [B*T, C]
    attn_kernel<<<dim3(TT / 128, HH, BB), 128>>>();

    // 3. Output projection + bias -> d_out
    sgemm_kernel<1><<<dim3(CCH / 64, MM / 128), 256>>>(nullptr, w_proj, b_proj, out, CCH);
}

// round 16
// speedup vs baseline: 1.0276x; 1.0276x over previous
#include <cuda_runtime.h>

// Problem constants
constexpr int BB = 2;
constexpr int TT = 2048;
constexpr int CCH = 1024;
constexpr int HH = 16;
constexpr int HD = 64;
constexpr int MM = BB * TT;   // 4096 rows

// Scratch (device globals: allowed; no cudaMalloc anywhere)
__device__ float g_Q[BB * HH * TT * HD];   // [B,H,T,HD]
__device__ float g_K[BB * HH * TT * HD];
__device__ float g_V[BB * HH * TT * HD];
__device__ float g_Y[MM * CCH];            // [B*T, C] attention output

// ---------------------------------------------------------------------------
// SGEMM: C[M,N] = A[M,K=1024] * W[1024,N] + bias[N]
// BM=128, BN=64, BK=16, 256 threads, 8x4 accum per thread.
// MODE 0: A = x param, scatter output into g_Q/g_K/g_V  (N=3072)
// MODE 1: A = g_Y,     write out[m*1024 + n]            (N=1024)
// ---------------------------------------------------------------------------
template <int MODE>
__global__ __launch_bounds__(256)
void sgemm_kernel(const float* __restrict__ A_in, const float* __restrict__ W,
                  const float* __restrict__ bias, float* __restrict__ out, int N)
{
    __shared__ float As[16][132];   // [k][m], padded
    __shared__ float Bs[16][68];    // [k][n], padded

    const float* __restrict__ A = (MODE == 0) ? A_in : g_Y;

    const int n0 = blockIdx.x * 64;
    const int m0 = blockIdx.y * 128;
    const int t  = threadIdx.x;
    const int tx = t & 15;          // 0..15 -> 4 cols each
    const int ty = t >> 4;          // 0..15 -> 8 rows each

    const int arow  = t >> 2;       // 0..63
    const int akcol = (t & 3) << 2; // 0,4,8,12
    const int brow  = t >> 4;       // 0..15
    const int bcol  = (t & 15) << 2;

    float acc[8][4] = {};

    for (int k0 = 0; k0 < CCH; k0 += 16) {
        const float4 a0 = *(const float4*)&A[(size_t)(m0 + arow) * CCH + k0 + akcol];
        const float4 a1 = *(const float4*)&A[(size_t)(m0 + arow + 64) * CCH + k0 + akcol];
        const float4 bv = *(const float4*)&W[(size_t)(k0 + brow) * N + n0 + bcol];

        __syncthreads();
        As[akcol + 0][arow]      = a0.x;
        As[akcol + 1][arow]      = a0.y;
        As[akcol + 2][arow]      = a0.z;
        As[akcol + 3][arow]      = a0.w;
        As[akcol + 0][arow + 64] = a1.x;
        As[akcol + 1][arow + 64] = a1.y;
        As[akcol + 2][arow + 64] = a1.z;
        As[akcol + 3][arow + 64] = a1.w;
        *(float4*)&Bs[brow][bcol] = bv;
        __syncthreads();

        #pragma unroll
        for (int kk = 0; kk < 16; kk++) {
            float a[8], bq[4];
            *(float4*)&a[0] = *(const float4*)&As[kk][ty * 8];
            *(float4*)&a[4] = *(const float4*)&As[kk][ty * 8 + 4];
            *(float4*)&bq[0] = *(const float4*)&Bs[kk][tx * 4];
            #pragma unroll
            for (int i = 0; i < 8; i++)
                #pragma unroll
                for (int j = 0; j < 4; j++)
                    acc[i][j] += a[i] * bq[j];
        }
    }

    const int n = n0 + tx * 4;
    const float4 bvec = *(const float4*)&bias[n];

    if (MODE == 0) {
        // n in [0,3072): section 0=Q,1=K,2=V; within section: head h, dim d
        const int sec = n >> 10;
        const int cc  = n & 1023;
        const int h   = cc >> 6;
        const int d   = cc & 63;
        float* dst = (sec == 0) ? g_Q : ((sec == 1) ? g_K : g_V);
        #pragma unroll
        for (int i = 0; i < 8; i++) {
            const int mg = m0 + ty * 8 + i;
            const int b_ = mg >> 11;          // /2048
            const int tt = mg & (TT - 1);
            float4 v;
            v.x = acc[i][0] + bvec.x;
            v.y = acc[i][1] + bvec.y;
            v.z = acc[i][2] + bvec.z;
            v.w = acc[i][3] + bvec.w;
            *(float4*)&dst[((size_t)((b_ * HH + h) * TT + tt)) * HD + d] = v;
        }
    } else {
        #pragma unroll
        for (int i = 0; i < 8; i++) {
            const int mg = m0 + ty * 8 + i;
            float4 v;
            v.x = acc[i][0] + bvec.x;
            v.y = acc[i][1] + bvec.y;
            v.z = acc[i][2] + bvec.z;
            v.w = acc[i][3] + bvec.w;
            *(float4*)&out[(size_t)mg * CCH + n] = v;
        }
    }
}

// ---------------------------------------------------------------------------
// Flash attention, fp32. One q-row per thread (128 rows / block), KT=32 K/V
// tiles in shared memory, online softmax. Causal. Writes g_Y[B*T, C].
// ---------------------------------------------------------------------------
constexpr int KT = 32;

__global__ __launch_bounds__(128)
void attn_kernel()
{
    __shared__ float Ks[KT * HD];
    __shared__ float Vs[KT * HD];

    const int tid = threadIdx.x;
    // reverse block order: largest (most k-tiles) blocks scheduled first
    const int q0 = (gridDim.x - 1 - blockIdx.x) * 128;
    const int h  = blockIdx.y;
    const int b  = blockIdx.z;
    const int tq = q0 + tid;

    const float* __restrict__ Qp = &g_Q[((size_t)(b * HH + h) * TT + tq) * HD];
    const float* __restrict__ Kbase = &g_K[(size_t)(b * HH + h) * TT * HD];
    const float* __restrict__ Vbase = &g_V[(size_t)(b * HH + h) * TT * HD];

    float q[HD];
    #pragma unroll
    for (int d = 0; d < HD; d += 4) {
        const float4 v = *(const float4*)&Qp[d];
        q[d] = v.x; q[d+1] = v.y; q[d+2] = v.z; q[d+3] = v.w;
    }

    float o[HD];
    #pragma unroll
    for (int d = 0; d < HD; d++) o[d] = 0.f;
    float mrun = -1e30f;
    float l = 0.f;

    const int ntiles = (q0 + 128) / KT;

    for (int kt = 0; kt < ntiles; kt++) {
        const int k0 = kt * KT;

        __syncthreads();
        {
            const float4* __restrict__ Ksrc = (const float4*)(Kbase + (size_t)k0 * HD);
            const float4* __restrict__ Vsrc = (const float4*)(Vbase + (size_t)k0 * HD);
            float4* Kd = (float4*)Ks;
            float4* Vd = (float4*)Vs;
            #pragma unroll
            for (int i = 0; i < (KT * HD / 4) / 128; i++) {
                Kd[tid + i * 128] = Ksrc[tid + i * 128];
                Vd[tid + i * 128] = Vsrc[tid + i * 128];
            }
        }
        __syncthreads();

        if (k0 <= tq) {
            float s[KT];
            #pragma unroll
            for (int j = 0; j < KT; j++) {
                const float* kr = &Ks[j * HD];
                float acc = 0.f;
                #pragma unroll
                for (int d = 0; d < HD; d += 4) {
                    const float4 kv = *(const float4*)&kr[d];
                    acc += q[d]   * kv.x;
                    acc += q[d+1] * kv.y;
                    acc += q[d+2] * kv.z;
                    acc += q[d+3] * kv.w;
                }
                s[j] = (k0 + j <= tq) ? acc * 0.125f : -1e30f;
            }

            float mt = mrun;
            #pragma unroll
            for (int j = 0; j < KT; j++) mt = fmaxf(mt, s[j]);

            const float scale_o = __expf(mrun - mt);
            mrun = mt;
            l *= scale_o;
            #pragma unroll
            for (int d = 0; d < HD; d++) o[d] *= scale_o;

            #pragma unroll
            for (int j = 0; j < KT; j++) {
                const float p = __expf(s[j] - mrun);
                l += p;
                const float* vr = &Vs[j * HD];
                #pragma unroll
                for (int d = 0; d < HD; d += 4) {
                    const float4 vv = *(const float4*)&vr[d];
                    o[d]   += p * vv.x;
                    o[d+1] += p * vv.y;
                    o[d+2] += p * vv.z;
                    o[d+3] += p * vv.w;
                }
            }
        }
    }

    const float inv = 1.f / l;
    float* Yp = &g_Y[((size_t)(b * TT + tq)) * CCH + h * HD];
    #pragma unroll
    for (int d = 0; d < HD; d += 4) {
        float4 v;
        v.x = o[d]   * inv;
        v.y = o[d+1] * inv;
        v.z = o[d+2] * inv;
        v.w = o[d+3] * inv;
        *(float4*)&Yp[d] = v;
    }
}

// ---------------------------------------------------------------------------
// kernel_launch — inputs: x, w_attn, b_attn, w_proj, b_proj ; out: [B,T,C] f32
// ---------------------------------------------------------------------------
extern "C" void kernel_launch(void* const* d_in, const int* in_sizes, int n_in,
                              void* d_out, int out_size)
{
    const float* x      = (const float*)d_in[0];
    const float* w_attn = (const float*)d_in[1];
    const float* b_attn = (const float*)d_in[2];
    const float* w_proj = (const float*)d_in[3];
    const float* b_proj = (const float*)d_in[4];
    float* out = (float*)d_out;

    // 1. QKV GEMM + bias, scattered to [B,H,T,HD] Q/K/V
    sgemm_kernel<0><<<dim3(3 * CCH / 64, MM / 128), 256>>>(x, w_attn, b_attn, nullptr, 3 * CCH);

    // 2. Causal flash attention -> g_Y [B*T, C]
    attn_kernel<<<dim3(TT / 128, HH, BB), 128>>>();

    // 3. Output projection + bias -> d_out
    sgemm_kernel<1><<<dim3(CCH / 64, MM / 128), 256>>>(nullptr, w_proj, b_proj, out, CCH);
}